// round 9
// baseline (speedup 1.0000x reference)
#include <cuda_runtime.h>
#include <math.h>

#define Bn 8
#define Hn 256
#define Wn 256
#define R  4
#define TRB 8                     // output rows per block
#define NROWS (TRB + 2*R)         // 16 halo rows (16-bit mask per column)
#define GW (Wn + 2*R)             // 264 padded words per row (idx = col + R)
#define NBLK (Bn * (Hn / TRB))    // 256 blocks
#define PADV 0x0FFF0FFFu          // "far" in both packed halves

// Per-block partials + completion counter. g_done is statically zero and is
// reset by the last block each launch, so graph replays start clean.
__device__ float g_part[NBLK];
__device__ unsigned int g_done = 0;

__device__ __forceinline__ int vdist16(unsigned int m, int p)
{
    const unsigned int down = m >> p;
    const unsigned int up   = m << (31 - p);
    const int dd = down ? (__ffs((int)down) - 1) : 63;
    const int du = up   ? __clz((int)up)         : 63;
    return min(dd, du);
}

__global__ void __launch_bounds__(256)
boundary_loss_kernel(const float* __restrict__ pred,
                     const float* __restrict__ targ,
                     float* __restrict__ out)
{
    const int tile = blockIdx.x;             // 0 .. 255
    const int b    = tile >> 5;              // 32 row-tiles per image
    const int h0   = (tile & 31) * TRB;      // first output row of this tile
    const int tx   = threadIdx.x;            // 0..63  (column group)
    const int ty   = threadIdx.y;            // 0..3   (row group)
    const int lin  = tx + (ty << 6);         // linear tid 0..255
    const int c0   = tx << 2;                // first of this thread's 4 cols

    __shared__ unsigned int sh[TRB][GW];     // packed (d2_bg | d2_fg<<16)
    __shared__ unsigned int cm[4][64];       // halo class nibbles per ty-slice
    __shared__ float lutW[34];
    __shared__ float ws[8];
    __shared__ int   s_last;

    const int base = b * (Hn * Wn);
    const float* pimg = pred + base;
    const uint4* timg = (const uint4*)(targ + base);   // 4 cols per element

    // ---- front-batch ALL global loads (6 x LDG.128 per thread) ----
    const int start = h0 - R;
    uint4 th[4];                             // halo rows start+4*ty+j, 4 cols
    #pragma unroll
    for (int j = 0; j < 4; ++j) {
        const int hh = min(max(start + 4 * ty + j, 0), Hn - 1);
        th[j] = __ldg(&timg[hh * (Wn / 4) + tx]);
    }
    const int r0 = 2 * ty;                   // this thread's 2 output rows
    float4 x0 = __ldg((const float4*)(pimg + (h0 + r0    ) * Wn + c0));
    float4 x1 = __ldg((const float4*)(pimg + (h0 + r0 + 1) * Wn + c0));

    // ---- LUT + pads while loads are in flight ----
    if (lin < 34) {
        const float d = (lin == 33) ? 64.0f : sqrtf((float)lin);
        lutW[lin] = 1.0f / (1.0f + __expf((d - 3.0f) * 0.2f));
    }
    if (ty == 0) {                           // 64 threads: 8 rows x 8 pads
        const int r = tx >> 3, i = tx & 7;
        const int idx = (i < R) ? i : (Wn + i);   // 0..3 / 260..263
        sh[r][idx] = PADV;
    }

    // ---- class nibbles: bit 23 of 0.0f/1.0f IS the class flag ----
    unsigned int nib = 0u;
    #pragma unroll
    for (int j = 0; j < 4; ++j) {
        nib |= ((th[j].x >> 23) & 1u) << (j);
        nib |= ((th[j].y >> 23) & 1u) << (4 + j);
        nib |= ((th[j].z >> 23) & 1u) << (8 + j);
        nib |= ((th[j].w >> 23) & 1u) << (12 + j);
    }
    cm[ty][tx] = nib;
    __syncthreads();

    // ---- assemble 16-bit column masks + validity ----
    unsigned int vm = 0xFFFFu;
    if (start < 0)          vm &= ~((1u << (-start)) - 1u);
    if (start + NROWS > Hn) vm &=  (1u << (Hn - start)) - 1u;

    const unsigned int q0 = cm[0][tx], q1 = cm[1][tx],
                       q2 = cm[2][tx], q3 = cm[3][tx];
    unsigned int fgm[4];
    #pragma unroll
    for (int cc = 0; cc < 4; ++cc) {
        unsigned int m = ((q0 >> (4 * cc)) & 0xFu)
                       | (((q1 >> (4 * cc)) & 0xFu) << 4)
                       | (((q2 >> (4 * cc)) & 0xFu) << 8)
                       | (((q3 >> (4 * cc)) & 0xFu) << 12);
        fgm[cc] = m & vm;
    }

    // ---- vertical pass: 2 rows x 4 cols, packed both classes ----
    #pragma unroll
    for (int rr = 0; rr < 2; ++rr) {
        const int r = r0 + rr;
        const int p = r + R;
        uint4 pk;
        unsigned int* pkp = (unsigned int*)&pk;
        #pragma unroll
        for (int cc = 0; cc < 4; ++cc) {
            const unsigned int fm = fgm[cc];
            const unsigned int bm = (~fm) & vm;
            const int dp = vdist16(bm, p);
            const int dn = vdist16(fm, p);
            pkp[cc] = (unsigned)(dp * dp) | ((unsigned)(dn * dn) << 16);
        }
        *(uint4*)&sh[r][c0 + R] = pk;        // 16B aligned (c0 mult of 4)
    }
    __syncthreads();

    // ---- horizontal 9-tap packed envelope + fused BCE * LUT weight ----
    float acc = 0.0f;
    #pragma unroll
    for (int rr = 0; rr < 2; ++rr) {
        const int r = r0 + rr;
        unsigned int v[12];
        #pragma unroll
        for (int i = 0; i < 12; i += 4)
            *(uint4*)&v[i] = *(const uint4*)&sh[r][c0 + i];

        const float4 xv = rr ? x1 : x0;
        const float xs[4] = {xv.x, xv.y, xv.z, xv.w};

        #pragma unroll
        for (int cc = 0; cc < 4; ++cc) {
            unsigned int best = 0xFFFFFFFFu;
            #pragma unroll
            for (int k = 0; k < 9; ++k) {
                const int kk = k - R;
                const unsigned int add = (unsigned)(kk * kk) * 0x00010001u;
                best = __vminu2(best, v[cc + k] + add);
            }
            const bool fg = (fgm[cc] >> (r + R)) & 1u;
            const unsigned int d2 = fg ? (best & 0xFFFFu) : (best >> 16);
            const float weight = lutW[min(d2, 33u)];

            const float x   = xs[cc];
            const float bce = fmaxf(x, 0.0f) - (fg ? x : 0.0f)
                            + __logf(1.0f + __expf(-fabsf(x)));
            acc = fmaf(bce, weight, acc);
        }
    }

    // ---- block reduction (8 warps) ----
    #pragma unroll
    for (int off = 16; off > 0; off >>= 1)
        acc += __shfl_xor_sync(0xffffffffu, acc, off);
    if ((lin & 31) == 0) ws[lin >> 5] = acc;
    __syncthreads();

    // ---- publish per-block partial (contention-free STG), then count ----
    if (lin == 0) {
        float s = 0.0f;
        #pragma unroll
        for (int i = 0; i < 8; ++i) s += ws[i];
        g_part[tile] = s;
        __threadfence();
        const unsigned int done = atomicAdd(&g_done, 1u);
        s_last = (done == (unsigned int)(NBLK - 1));
    }
    __syncthreads();

    // ---- last block: reduce the 256 partials and finalize ----
    if (s_last) {
        __threadfence();                     // acquire partials
        float s = g_part[lin];
        #pragma unroll
        for (int off = 16; off > 0; off >>= 1)
            s += __shfl_xor_sync(0xffffffffu, s, off);
        if ((lin & 31) == 0) ws[lin >> 5] = s;
        __syncthreads();
        if (lin == 0) {
            float tot = 0.0f;
            #pragma unroll
            for (int i = 0; i < 8; ++i) tot += ws[i];
            out[0] = tot * (1.0f / (float)(Bn * Hn * Wn));
            g_done = 0u;                     // reset for next launch / replay
        }
    }
}

extern "C" void kernel_launch(void* const* d_in, const int* in_sizes, int n_in,
                              void* d_out, int out_size)
{
    const float* pred = (const float*)d_in[0];
    const float* targ = (const float*)d_in[1];
    float* out = (float*)d_out;

    dim3 blk(64, 4);
    boundary_loss_kernel<<<NBLK, blk>>>(pred, targ, out);
}